// round 3
// baseline (speedup 1.0000x reference)
#include <cuda_runtime.h>
#include <cstdint>

#define N_MAX 100000
#define D 128

// Scratch (static device globals — allocation-free per harness rules)
__device__ float g_buf[N_MAX * D];   // g[u] = dinv[u] * (x@W)[u]
__device__ float g_acc[N_MAX * D];   // accumulator (init = g -> self-loop)
__device__ float g_x[N_MAX * D];     // ping buffer for layer outputs
__device__ float g_dinv[N_MAX];
__device__ int   g_deg[N_MAX];

// ---------------- degree / dinv ----------------
__global__ void deg_init(int n) {
    int i = blockIdx.x * blockDim.x + threadIdx.x;
    if (i < n) g_deg[i] = 1;  // self-loop
}

__global__ void deg_count(const int* __restrict__ dst, int E) {
    int i = blockIdx.x * blockDim.x + threadIdx.x;
    if (i < E) atomicAdd(&g_deg[__ldg(&dst[i])], 1);
}

__global__ void dinv_kernel(int n) {
    int i = blockIdx.x * blockDim.x + threadIdx.x;
    if (i < n) g_dinv[i] = rsqrtf((float)g_deg[i]);
}

// ---------------- GEMM: g = dinv .* (X @ W), also acc = g ----------------
// Tile: 128 rows x full D cols, K chunked by 32. 256 threads, 8x8 microtile.
#define TM 128
#define TK 32
#define APAD 4

template <bool FROM_GX>
__global__ __launch_bounds__(256, 2)
void gemm_scale(const float* __restrict__ Xin, const float* __restrict__ W, int nrows) {
    __shared__ float As[TK][TM + APAD];   // transposed: As[k][m]
    __shared__ float Bs[TK][D];

    const float* X = FROM_GX ? g_x : Xin;

    const int m0  = blockIdx.x * TM;
    const int tid = threadIdx.x;
    const int tx  = tid & 15;          // col group 0..15
    const int ty  = tid >> 4;          // row group 0..15

    float acc[8][8];
    #pragma unroll
    for (int i = 0; i < 8; i++)
        #pragma unroll
        for (int j = 0; j < 8; j++) acc[i][j] = 0.f;

    for (int k0 = 0; k0 < D; k0 += TK) {
        // load A tile [128 rows x 32 k], store transposed
        #pragma unroll
        for (int i = 0; i < 4; i++) {
            int id  = tid + i * 256;       // 0..1023
            int row = id >> 3;             // 128 rows
            int kq  = id & 7;              // 8 float4 per row
            float4 v = make_float4(0.f, 0.f, 0.f, 0.f);
            int gr = m0 + row;
            if (gr < nrows) v = *(const float4*)&X[(size_t)gr * D + k0 + kq * 4];
            As[kq * 4 + 0][row] = v.x;
            As[kq * 4 + 1][row] = v.y;
            As[kq * 4 + 2][row] = v.z;
            As[kq * 4 + 3][row] = v.w;
        }
        // load B tile [32 k x 128 cols]
        #pragma unroll
        for (int i = 0; i < 4; i++) {
            int id = tid + i * 256;
            int kr = id >> 5;              // 32 k rows
            int cq = id & 31;              // 32 float4 per row
            *(float4*)&Bs[kr][cq * 4] =
                *(const float4*)&W[(size_t)(k0 + kr) * D + cq * 4];
        }
        __syncthreads();

        #pragma unroll
        for (int kk = 0; kk < TK; kk++) {
            float a[8], b[8];
            *(float4*)&a[0] = *(float4*)&As[kk][ty * 8];
            *(float4*)&a[4] = *(float4*)&As[kk][ty * 8 + 4];
            *(float4*)&b[0] = *(float4*)&Bs[kk][tx * 8];
            *(float4*)&b[4] = *(float4*)&Bs[kk][tx * 8 + 4];
            #pragma unroll
            for (int i = 0; i < 8; i++)
                #pragma unroll
                for (int j = 0; j < 8; j++)
                    acc[i][j] = fmaf(a[i], b[j], acc[i][j]);
        }
        __syncthreads();
    }

    // epilogue: scale by dinv[row], write g_buf and g_acc (self-loop init)
    #pragma unroll
    for (int i = 0; i < 8; i++) {
        int gr = m0 + ty * 8 + i;
        if (gr >= nrows) continue;
        float dv = g_dinv[gr];
        size_t base = (size_t)gr * D + tx * 8;
        #pragma unroll
        for (int j4 = 0; j4 < 2; j4++) {
            float4 v;
            v.x = dv * acc[i][j4 * 4 + 0];
            v.y = dv * acc[i][j4 * 4 + 1];
            v.z = dv * acc[i][j4 * 4 + 2];
            v.w = dv * acc[i][j4 * 4 + 3];
            *(float4*)&g_buf[base + j4 * 4] = v;
            *(float4*)&g_acc[base + j4 * 4] = v;
        }
    }
}

// ---------------- edge scatter: acc[dst] += g[src] ----------------
// One warp per edge; each lane moves a float4 worth (4 scalar REDs).
__global__ __launch_bounds__(256)
void scatter_edges(const int* __restrict__ src,
                   const int* __restrict__ dst, int E) {
    int w    = (blockIdx.x * blockDim.x + threadIdx.x) >> 5;
    int lane = threadIdx.x & 31;
    if (w >= E) return;
    int s = __ldg(&src[w]);
    int d = __ldg(&dst[w]);
    float4 v = *(const float4*)&g_buf[(size_t)s * D + lane * 4];
    float* a = &g_acc[(size_t)d * D + lane * 4];
    atomicAdd(a + 0, v.x);
    atomicAdd(a + 1, v.y);
    atomicAdd(a + 2, v.z);
    atomicAdd(a + 3, v.w);
}

// ---------------- finalize: out = relu(dinv[v]*acc[v] + b) ----------------
template <bool TO_GX>
__global__ __launch_bounds__(256)
void finalize(const float* __restrict__ bias, float* __restrict__ outp, int nrows) {
    int idx = blockIdx.x * blockDim.x + threadIdx.x;   // over nrows*32
    if (idx >= nrows * 32) return;
    int v = idx >> 5;
    int q = idx & 31;
    float dv = g_dinv[v];
    float4 a = *(const float4*)&g_acc[(size_t)v * D + q * 4];
    float4 b = *(const float4*)&bias[q * 4];
    float4 r;
    r.x = fmaxf(fmaf(dv, a.x, b.x), 0.f);
    r.y = fmaxf(fmaf(dv, a.y, b.y), 0.f);
    r.z = fmaxf(fmaf(dv, a.z, b.z), 0.f);
    r.w = fmaxf(fmaf(dv, a.w, b.w), 0.f);
    float* out = TO_GX ? g_x : outp;
    *(float4*)&out[(size_t)v * D + q * 4] = r;
}

// ---------------- launch ----------------
extern "C" void kernel_launch(void* const* d_in, const int* in_sizes, int n_in,
                              void* d_out, int out_size) {
    const float* node_fts = (const float*)d_in[0];
    const int*   edge     = (const int*)d_in[1];   // int32 (JAX default x32)
    const float* W[3] = { (const float*)d_in[2], (const float*)d_in[4], (const float*)d_in[6] };
    const float* B[3] = { (const float*)d_in[3], (const float*)d_in[5], (const float*)d_in[7] };

    const int nrows = in_sizes[0] / D;
    const int E     = in_sizes[1] / 2;
    const int* src  = edge;
    const int* dst  = edge + E;

    // degrees / dinv (deterministic recompute each call)
    deg_init<<<(nrows + 255) / 256, 256>>>(nrows);
    deg_count<<<(E + 255) / 256, 256>>>(dst, E);
    dinv_kernel<<<(nrows + 255) / 256, 256>>>(nrows);

    const int gemm_blocks = (nrows + TM - 1) / TM;
    const int scat_blocks = (E * 32 + 255) / 256;
    const int fin_blocks  = (nrows * 32 + 255) / 256;

    // Layer 1: read node_fts, write g_x
    gemm_scale<false><<<gemm_blocks, 256>>>(node_fts, W[0], nrows);
    scatter_edges<<<scat_blocks, 256>>>(src, dst, E);
    finalize<true><<<fin_blocks, 256>>>(B[0], nullptr, nrows);

    // Layer 2: read g_x, write g_x
    gemm_scale<true><<<gemm_blocks, 256>>>(nullptr, W[1], nrows);
    scatter_edges<<<scat_blocks, 256>>>(src, dst, E);
    finalize<true><<<fin_blocks, 256>>>(B[1], nullptr, nrows);

    // Layer 3: read g_x, write d_out
    gemm_scale<true><<<gemm_blocks, 256>>>(nullptr, W[2], nrows);
    scatter_edges<<<scat_blocks, 256>>>(src, dst, E);
    finalize<false><<<fin_blocks, 256>>>(B[2], (float*)d_out, nrows);
}

// round 4
// speedup vs baseline: 1.7547x; 1.7547x over previous
#include <cuda_runtime.h>
#include <cstdint>

#define N_MAX 100000
#define D 128

// Scratch (static device globals — allocation-free per harness rules)
__device__ float g_buf[N_MAX * D];   // g[u] = dinv[u] * (x@W)[u]
__device__ float g_acc[N_MAX * D];   // accumulator (init = g -> self-loop)
__device__ float g_x[N_MAX * D];     // ping buffer for layer outputs
__device__ float g_dinv[N_MAX];
__device__ int   g_deg[N_MAX];

// ---------------- degree / dinv ----------------
__global__ void deg_init(int n) {
    int i = blockIdx.x * blockDim.x + threadIdx.x;
    if (i < n) g_deg[i] = 1;  // self-loop
}

__global__ void deg_count(const int* __restrict__ dst, int E) {
    int i = blockIdx.x * blockDim.x + threadIdx.x;
    if (i < E) atomicAdd(&g_deg[__ldg(&dst[i])], 1);
}

__global__ void dinv_kernel(int n) {
    int i = blockIdx.x * blockDim.x + threadIdx.x;
    if (i < n) g_dinv[i] = rsqrtf((float)g_deg[i]);
}

// ---------------- GEMM: g = dinv .* (X @ W), also acc = g ----------------
// Tile: 128 rows x full D cols, K chunked by 32. 256 threads, 8x8 microtile.
#define TM 128
#define TK 32
#define APAD 4

template <bool FROM_GX>
__global__ __launch_bounds__(256, 2)
void gemm_scale(const float* __restrict__ Xin, const float* __restrict__ W, int nrows) {
    __shared__ float As[TK][TM + APAD];   // transposed: As[k][m]
    __shared__ float Bs[TK][D];

    const float* X = FROM_GX ? g_x : Xin;

    const int m0  = blockIdx.x * TM;
    const int tid = threadIdx.x;
    const int tx  = tid & 15;          // col group 0..15
    const int ty  = tid >> 4;          // row group 0..15

    float acc[8][8];
    #pragma unroll
    for (int i = 0; i < 8; i++)
        #pragma unroll
        for (int j = 0; j < 8; j++) acc[i][j] = 0.f;

    for (int k0 = 0; k0 < D; k0 += TK) {
        // load A tile [128 rows x 32 k], store transposed
        #pragma unroll
        for (int i = 0; i < 4; i++) {
            int id  = tid + i * 256;       // 0..1023
            int row = id >> 3;             // 128 rows
            int kq  = id & 7;              // 8 float4 per row
            float4 v = make_float4(0.f, 0.f, 0.f, 0.f);
            int gr = m0 + row;
            if (gr < nrows) v = *(const float4*)&X[(size_t)gr * D + k0 + kq * 4];
            As[kq * 4 + 0][row] = v.x;
            As[kq * 4 + 1][row] = v.y;
            As[kq * 4 + 2][row] = v.z;
            As[kq * 4 + 3][row] = v.w;
        }
        // load B tile [32 k x 128 cols]
        #pragma unroll
        for (int i = 0; i < 4; i++) {
            int id = tid + i * 256;
            int kr = id >> 5;              // 32 k rows
            int cq = id & 31;              // 32 float4 per row
            *(float4*)&Bs[kr][cq * 4] =
                *(const float4*)&W[(size_t)(k0 + kr) * D + cq * 4];
        }
        __syncthreads();

        #pragma unroll
        for (int kk = 0; kk < TK; kk++) {
            float a[8], b[8];
            *(float4*)&a[0] = *(float4*)&As[kk][ty * 8];
            *(float4*)&a[4] = *(float4*)&As[kk][ty * 8 + 4];
            *(float4*)&b[0] = *(float4*)&Bs[kk][tx * 8];
            *(float4*)&b[4] = *(float4*)&Bs[kk][tx * 8 + 4];
            #pragma unroll
            for (int i = 0; i < 8; i++)
                #pragma unroll
                for (int j = 0; j < 8; j++)
                    acc[i][j] = fmaf(a[i], b[j], acc[i][j]);
        }
        __syncthreads();
    }

    // epilogue: scale by dinv[row], write g_buf and g_acc (self-loop init)
    #pragma unroll
    for (int i = 0; i < 8; i++) {
        int gr = m0 + ty * 8 + i;
        if (gr >= nrows) continue;
        float dv = g_dinv[gr];
        size_t base = (size_t)gr * D + tx * 8;
        #pragma unroll
        for (int j4 = 0; j4 < 2; j4++) {
            float4 v;
            v.x = dv * acc[i][j4 * 4 + 0];
            v.y = dv * acc[i][j4 * 4 + 1];
            v.z = dv * acc[i][j4 * 4 + 2];
            v.w = dv * acc[i][j4 * 4 + 3];
            *(float4*)&g_buf[base + j4 * 4] = v;
            *(float4*)&g_acc[base + j4 * 4] = v;
        }
    }
}

// ---------------- edge scatter: acc[dst] += g[src] ----------------
// One warp per edge; each lane moves one float4 via a single vector RED (16B).
__global__ __launch_bounds__(256)
void scatter_edges(const int* __restrict__ src,
                   const int* __restrict__ dst, int E) {
    int w    = (blockIdx.x * blockDim.x + threadIdx.x) >> 5;
    int lane = threadIdx.x & 31;
    if (w >= E) return;
    int s = __ldg(&src[w]);
    int d = __ldg(&dst[w]);
    float4 v = *(const float4*)&g_buf[(size_t)s * D + lane * 4];
    float* a = &g_acc[(size_t)d * D + lane * 4];
    asm volatile("red.global.add.v4.f32 [%0], {%1, %2, %3, %4};"
                 :: "l"(a), "f"(v.x), "f"(v.y), "f"(v.z), "f"(v.w)
                 : "memory");
}

// ---------------- finalize: out = relu(dinv[v]*acc[v] + b) ----------------
template <bool TO_GX>
__global__ __launch_bounds__(256)
void finalize(const float* __restrict__ bias, float* __restrict__ outp, int nrows) {
    int idx = blockIdx.x * blockDim.x + threadIdx.x;   // over nrows*32
    if (idx >= nrows * 32) return;
    int v = idx >> 5;
    int q = idx & 31;
    float dv = g_dinv[v];
    float4 a = *(const float4*)&g_acc[(size_t)v * D + q * 4];
    float4 b = *(const float4*)&bias[q * 4];
    float4 r;
    r.x = fmaxf(fmaf(dv, a.x, b.x), 0.f);
    r.y = fmaxf(fmaf(dv, a.y, b.y), 0.f);
    r.z = fmaxf(fmaf(dv, a.z, b.z), 0.f);
    r.w = fmaxf(fmaf(dv, a.w, b.w), 0.f);
    float* out = TO_GX ? g_x : outp;
    *(float4*)&out[(size_t)v * D + q * 4] = r;
}

// ---------------- launch ----------------
extern "C" void kernel_launch(void* const* d_in, const int* in_sizes, int n_in,
                              void* d_out, int out_size) {
    const float* node_fts = (const float*)d_in[0];
    const int*   edge     = (const int*)d_in[1];   // int32 (JAX default x32)
    const float* W[3] = { (const float*)d_in[2], (const float*)d_in[4], (const float*)d_in[6] };
    const float* B[3] = { (const float*)d_in[3], (const float*)d_in[5], (const float*)d_in[7] };

    const int nrows = in_sizes[0] / D;
    const int E     = in_sizes[1] / 2;
    const int* src  = edge;
    const int* dst  = edge + E;

    // degrees / dinv (deterministic recompute each call)
    deg_init<<<(nrows + 255) / 256, 256>>>(nrows);
    deg_count<<<(E + 255) / 256, 256>>>(dst, E);
    dinv_kernel<<<(nrows + 255) / 256, 256>>>(nrows);

    const int gemm_blocks = (nrows + TM - 1) / TM;
    const int scat_blocks = (E * 32 + 255) / 256;
    const int fin_blocks  = (nrows * 32 + 255) / 256;

    // Layer 1: read node_fts, write g_x
    gemm_scale<false><<<gemm_blocks, 256>>>(node_fts, W[0], nrows);
    scatter_edges<<<scat_blocks, 256>>>(src, dst, E);
    finalize<true><<<fin_blocks, 256>>>(B[0], nullptr, nrows);

    // Layer 2: read g_x, write g_x
    gemm_scale<true><<<gemm_blocks, 256>>>(nullptr, W[1], nrows);
    scatter_edges<<<scat_blocks, 256>>>(src, dst, E);
    finalize<true><<<fin_blocks, 256>>>(B[1], nullptr, nrows);

    // Layer 3: read g_x, write d_out
    gemm_scale<true><<<gemm_blocks, 256>>>(nullptr, W[2], nrows);
    scatter_edges<<<scat_blocks, 256>>>(src, dst, E);
    finalize<false><<<fin_blocks, 256>>>(B[2], (float*)d_out, nrows);
}

// round 5
// speedup vs baseline: 3.5863x; 2.0438x over previous
#include <cuda_runtime.h>
#include <cstdint>

#define N_MAX 100000
#define E_MAX 1700000
#define D 128
#define SCAN_B 1024
#define MAX_BLOCKS 128   // ceil(N_MAX/SCAN_B) = 98

// Scratch (static device globals — allocation-free per harness rules)
__device__ float g_buf[N_MAX * D];       // g[u] = dinv[u] * (x@W)[u]
__device__ float g_x[N_MAX * D];         // ping buffer for layer outputs
__device__ float g_dinv[N_MAX];
__device__ int   g_cnt[N_MAX];           // in-degree (real edges only)
__device__ int   g_rowptr[N_MAX + 1];
__device__ int   g_cursor[N_MAX];
__device__ int   g_blocksum[MAX_BLOCKS];
__device__ int   g_blockoff[MAX_BLOCKS];
__device__ int   g_csr[E_MAX];           // src indices grouped by dst

// ---------------- degree histogram ----------------
__global__ void cnt_zero(int n) {
    int i = blockIdx.x * blockDim.x + threadIdx.x;
    if (i < n) g_cnt[i] = 0;
}

__global__ void cnt_count(const int* __restrict__ dst, int E) {
    int i = blockIdx.x * blockDim.x + threadIdx.x;
    if (i < E) atomicAdd(&g_cnt[__ldg(&dst[i])], 1);
}

// ---------------- prefix scan (3 phases) ----------------
__global__ void scanA(int n) {
    __shared__ int s[SCAN_B];
    int i = blockIdx.x * SCAN_B + threadIdx.x;
    s[threadIdx.x] = (i < n) ? g_cnt[i] : 0;
    __syncthreads();
    for (int off = SCAN_B / 2; off > 0; off >>= 1) {
        if (threadIdx.x < off) s[threadIdx.x] += s[threadIdx.x + off];
        __syncthreads();
    }
    if (threadIdx.x == 0) g_blocksum[blockIdx.x] = s[0];
}

__global__ void scanB(int nblocks, int n) {
    if (threadIdx.x == 0) {
        int acc = 0;
        for (int b = 0; b < nblocks; b++) { g_blockoff[b] = acc; acc += g_blocksum[b]; }
        g_rowptr[n] = acc;
    }
}

__global__ void scanC(int n) {
    __shared__ int s[SCAN_B];
    int i = blockIdx.x * SCAN_B + threadIdx.x;
    int v = (i < n) ? g_cnt[i] : 0;
    s[threadIdx.x] = v;
    __syncthreads();
    // Hillis-Steele inclusive scan
    for (int off = 1; off < SCAN_B; off <<= 1) {
        int t = (threadIdx.x >= off) ? s[threadIdx.x - off] : 0;
        __syncthreads();
        s[threadIdx.x] += t;
        __syncthreads();
    }
    if (i < n) {
        int excl = s[threadIdx.x] - v + g_blockoff[blockIdx.x];
        g_rowptr[i] = excl;
        g_cursor[i] = excl;
        g_dinv[i]   = rsqrtf((float)(v + 1));   // +1 self-loop
    }
}

__global__ void fill_csr(const int* __restrict__ src, const int* __restrict__ dst, int E) {
    int i = blockIdx.x * blockDim.x + threadIdx.x;
    if (i < E) {
        int d = __ldg(&dst[i]);
        int pos = atomicAdd(&g_cursor[d], 1);
        g_csr[pos] = __ldg(&src[i]);
    }
}

// ---------------- GEMM: g_buf = dinv .* (X @ W) ----------------
#define TM 128
#define TK 32
#define APAD 4

template <bool FROM_GX>
__global__ __launch_bounds__(256, 2)
void gemm_scale(const float* __restrict__ Xin, const float* __restrict__ W, int nrows) {
    __shared__ float As[TK][TM + APAD];   // transposed: As[k][m]
    __shared__ float Bs[TK][D];

    const float* X = FROM_GX ? g_x : Xin;

    const int m0  = blockIdx.x * TM;
    const int tid = threadIdx.x;
    const int tx  = tid & 15;
    const int ty  = tid >> 4;

    float acc[8][8];
    #pragma unroll
    for (int i = 0; i < 8; i++)
        #pragma unroll
        for (int j = 0; j < 8; j++) acc[i][j] = 0.f;

    for (int k0 = 0; k0 < D; k0 += TK) {
        #pragma unroll
        for (int i = 0; i < 4; i++) {
            int id  = tid + i * 256;
            int row = id >> 3;
            int kq  = id & 7;
            float4 v = make_float4(0.f, 0.f, 0.f, 0.f);
            int gr = m0 + row;
            if (gr < nrows) v = *(const float4*)&X[(size_t)gr * D + k0 + kq * 4];
            As[kq * 4 + 0][row] = v.x;
            As[kq * 4 + 1][row] = v.y;
            As[kq * 4 + 2][row] = v.z;
            As[kq * 4 + 3][row] = v.w;
        }
        #pragma unroll
        for (int i = 0; i < 4; i++) {
            int id = tid + i * 256;
            int kr = id >> 5;
            int cq = id & 31;
            *(float4*)&Bs[kr][cq * 4] =
                *(const float4*)&W[(size_t)(k0 + kr) * D + cq * 4];
        }
        __syncthreads();

        #pragma unroll
        for (int kk = 0; kk < TK; kk++) {
            float a[8], b[8];
            *(float4*)&a[0] = *(float4*)&As[kk][ty * 8];
            *(float4*)&a[4] = *(float4*)&As[kk][ty * 8 + 4];
            *(float4*)&b[0] = *(float4*)&Bs[kk][tx * 8];
            *(float4*)&b[4] = *(float4*)&Bs[kk][tx * 8 + 4];
            #pragma unroll
            for (int i = 0; i < 8; i++)
                #pragma unroll
                for (int j = 0; j < 8; j++)
                    acc[i][j] = fmaf(a[i], b[j], acc[i][j]);
        }
        __syncthreads();
    }

    #pragma unroll
    for (int i = 0; i < 8; i++) {
        int gr = m0 + ty * 8 + i;
        if (gr >= nrows) continue;
        float dv = g_dinv[gr];
        size_t base = (size_t)gr * D + tx * 8;
        #pragma unroll
        for (int j4 = 0; j4 < 2; j4++) {
            float4 v;
            v.x = dv * acc[i][j4 * 4 + 0];
            v.y = dv * acc[i][j4 * 4 + 1];
            v.z = dv * acc[i][j4 * 4 + 2];
            v.w = dv * acc[i][j4 * 4 + 3];
            *(float4*)&g_buf[base + j4 * 4] = v;
        }
    }
}

// ---------------- aggregate: out[v] = relu(dinv[v]*(g[v] + sum g[nbr]) + b) ----------------
// One warp per dst node; lane covers float4 (32 lanes x 16B = full row).
template <bool TO_GX>
__global__ __launch_bounds__(256)
void aggregate(const float* __restrict__ bias, float* __restrict__ outp, int n) {
    int w    = (blockIdx.x * blockDim.x + threadIdx.x) >> 5;
    int lane = threadIdx.x & 31;
    if (w >= n) return;

    int beg = g_rowptr[w];
    int end = g_rowptr[w + 1];
    size_t col = (size_t)lane * 4;

    // self-loop term
    float4 acc = *(const float4*)&g_buf[(size_t)w * D + col];

    int e = beg;
    for (; e + 2 <= end; e += 2) {
        int s0 = __ldg(&g_csr[e]);
        int s1 = __ldg(&g_csr[e + 1]);
        float4 v0 = *(const float4*)&g_buf[(size_t)s0 * D + col];
        float4 v1 = *(const float4*)&g_buf[(size_t)s1 * D + col];
        acc.x += v0.x + v1.x;
        acc.y += v0.y + v1.y;
        acc.z += v0.z + v1.z;
        acc.w += v0.w + v1.w;
    }
    if (e < end) {
        int s0 = __ldg(&g_csr[e]);
        float4 v0 = *(const float4*)&g_buf[(size_t)s0 * D + col];
        acc.x += v0.x; acc.y += v0.y; acc.z += v0.z; acc.w += v0.w;
    }

    float dv = g_dinv[w];
    float4 b = *(const float4*)&bias[col];
    float4 r;
    r.x = fmaxf(fmaf(dv, acc.x, b.x), 0.f);
    r.y = fmaxf(fmaf(dv, acc.y, b.y), 0.f);
    r.z = fmaxf(fmaf(dv, acc.z, b.z), 0.f);
    r.w = fmaxf(fmaf(dv, acc.w, b.w), 0.f);

    float* out = TO_GX ? g_x : outp;
    *(float4*)&out[(size_t)w * D + col] = r;
}

// ---------------- launch ----------------
extern "C" void kernel_launch(void* const* d_in, const int* in_sizes, int n_in,
                              void* d_out, int out_size) {
    const float* node_fts = (const float*)d_in[0];
    const int*   edge     = (const int*)d_in[1];   // int32
    const float* W[3] = { (const float*)d_in[2], (const float*)d_in[4], (const float*)d_in[6] };
    const float* B[3] = { (const float*)d_in[3], (const float*)d_in[5], (const float*)d_in[7] };

    const int nrows = in_sizes[0] / D;
    const int E     = in_sizes[1] / 2;
    const int* src  = edge;
    const int* dst  = edge + E;

    const int scan_blocks = (nrows + SCAN_B - 1) / SCAN_B;

    // ---- CSR build (once per call, reused by all 3 layers) ----
    cnt_zero<<<(nrows + 255) / 256, 256>>>(nrows);
    cnt_count<<<(E + 255) / 256, 256>>>(dst, E);
    scanA<<<scan_blocks, SCAN_B>>>(nrows);
    scanB<<<1, 32>>>(scan_blocks, nrows);
    scanC<<<scan_blocks, SCAN_B>>>(nrows);
    fill_csr<<<(E + 255) / 256, 256>>>(src, dst, E);

    const int gemm_blocks = (nrows + TM - 1) / TM;
    const int agg_blocks  = (nrows * 32 + 255) / 256;

    // Layer 1: read node_fts -> g_x
    gemm_scale<false><<<gemm_blocks, 256>>>(node_fts, W[0], nrows);
    aggregate<true><<<agg_blocks, 256>>>(B[0], nullptr, nrows);

    // Layer 2: g_x -> g_x
    gemm_scale<true><<<gemm_blocks, 256>>>(nullptr, W[1], nrows);
    aggregate<true><<<agg_blocks, 256>>>(B[1], nullptr, nrows);

    // Layer 3: g_x -> d_out
    gemm_scale<true><<<gemm_blocks, 256>>>(nullptr, W[2], nrows);
    aggregate<false><<<agg_blocks, 256>>>(B[2], (float*)d_out, nrows);
}

// round 7
// speedup vs baseline: 4.4363x; 1.2370x over previous
#include <cuda_runtime.h>
#include <cuda_bf16.h>
#include <cstdint>

#define N_MAX 100000
#define E_MAX 1700000
#define D 128
#define SCAN_B 1024
#define MAX_BLOCKS 128   // >= ceil(N_MAX/SCAN_B) = 98, power of two for scanB

// ---------------- scratch (static device globals) ----------------
__device__ __align__(16) float g_buf[N_MAX * D];   // g[u] = dinv[u] * (x@W)[u]
__device__ __align__(16) float g_x[N_MAX * D];     // ping buffer for layer outputs
__device__ float g_dinv[N_MAX];
__device__ int   g_cnt[N_MAX];
__device__ int   g_rowptr[N_MAX + 1];
__device__ int   g_cursor[N_MAX];
__device__ int   g_blocksum[MAX_BLOCKS];
__device__ int   g_blockoff[MAX_BLOCKS];
__device__ int   g_csr[E_MAX];
__device__ __align__(16) __nv_bfloat16 g_wt_hi[3 * D * D];  // W^T hi split, [l][n][k]
__device__ __align__(16) __nv_bfloat16 g_wt_lo[3 * D * D];  // W^T lo split

// ---------------- degree histogram / scan / CSR ----------------
__global__ void cnt_zero(int n) {
    int i = blockIdx.x * blockDim.x + threadIdx.x;
    if (i < n) g_cnt[i] = 0;
}
__global__ void cnt_count(const int* __restrict__ dst, int E) {
    int i = blockIdx.x * blockDim.x + threadIdx.x;
    if (i < E) atomicAdd(&g_cnt[__ldg(&dst[i])], 1);
}
__global__ void scanA(int n) {
    __shared__ int s[SCAN_B];
    int i = blockIdx.x * SCAN_B + threadIdx.x;
    s[threadIdx.x] = (i < n) ? g_cnt[i] : 0;
    __syncthreads();
    for (int off = SCAN_B / 2; off > 0; off >>= 1) {
        if (threadIdx.x < off) s[threadIdx.x] += s[threadIdx.x + off];
        __syncthreads();
    }
    if (threadIdx.x == 0) g_blocksum[blockIdx.x] = s[0];
}
__global__ void scanB(int nblocks, int n) {
    __shared__ int s[MAX_BLOCKS];
    int t = threadIdx.x;
    int v = (t < nblocks) ? g_blocksum[t] : 0;
    s[t] = v; __syncthreads();
    for (int off = 1; off < MAX_BLOCKS; off <<= 1) {
        int u = (t >= off) ? s[t - off] : 0;
        __syncthreads();
        s[t] += u;
        __syncthreads();
    }
    if (t < nblocks) g_blockoff[t] = s[t] - v;
    if (t == nblocks - 1) g_rowptr[n] = s[t];
}
__global__ void scanC(int n) {
    __shared__ int s[SCAN_B];
    int i = blockIdx.x * SCAN_B + threadIdx.x;
    int v = (i < n) ? g_cnt[i] : 0;
    s[threadIdx.x] = v;
    __syncthreads();
    for (int off = 1; off < SCAN_B; off <<= 1) {
        int t = (threadIdx.x >= off) ? s[threadIdx.x - off] : 0;
        __syncthreads();
        s[threadIdx.x] += t;
        __syncthreads();
    }
    if (i < n) {
        int excl = s[threadIdx.x] - v + g_blockoff[blockIdx.x];
        g_rowptr[i] = excl;
        g_cursor[i] = excl;
        g_dinv[i]   = rsqrtf((float)(v + 1));
    }
}
__global__ void fill_csr(const int* __restrict__ src, const int* __restrict__ dst, int E) {
    int i = blockIdx.x * blockDim.x + threadIdx.x;
    if (i < E) {
        int d = __ldg(&dst[i]);
        int pos = atomicAdd(&g_cursor[d], 1);
        g_csr[pos] = __ldg(&src[i]);
    }
}

// ---------------- W^T split prep (once per call) ----------------
__global__ void prep_wt(const float* __restrict__ W0, const float* __restrict__ W1,
                        const float* __restrict__ W2) {
    int idx = blockIdx.x * blockDim.x + threadIdx.x;
    if (idx >= 3 * D * D) return;
    int l = idx / (D * D);
    int r = idx % (D * D);
    int n = r >> 7, k = r & 127;
    const float* W = (l == 0) ? W0 : ((l == 1) ? W1 : W2);
    float f = W[k * D + n];
    __nv_bfloat16 h = __float2bfloat16(f);
    float lo = f - __bfloat162float(h);
    g_wt_hi[idx] = h;
    g_wt_lo[idx] = __float2bfloat16(lo);
}

// ---------------- bf16x3 GEMM via mma.sync (HMMA, baseline PTX) ----------------
// g_buf = dinv .* (X @ W). CTA: 128x128 tile, 512 threads = 16 warps (4m x 4n),
// warp tile 32x32 = 2 x 4 m16n8k16 tiles. 3-term split Ah*Bh + Ah*Bl + Al*Bh.
#define PITCH 68   // b32 per smem row (136 bf16): bank = (4*g + tig) % 32, conflict-free
#define SM_TILE_B32 (128 * PITCH)
#define SM_TOTAL (4 * SM_TILE_B32 * 4)   // 139264 bytes

__device__ __forceinline__ void mma16816(float* c, const uint32_t* a, const uint32_t* b) {
    asm volatile(
        "mma.sync.aligned.m16n8k16.row.col.f32.bf16.bf16.f32 "
        "{%0,%1,%2,%3}, {%4,%5,%6,%7}, {%8,%9}, {%0,%1,%2,%3};"
        : "+f"(c[0]), "+f"(c[1]), "+f"(c[2]), "+f"(c[3])
        : "r"(a[0]), "r"(a[1]), "r"(a[2]), "r"(a[3]), "r"(b[0]), "r"(b[1]));
}

template <bool FROM_GX>
__global__ __launch_bounds__(512)
void gemm_mma(const float* __restrict__ Xin, int layer, int nrows) {
    extern __shared__ uint32_t smem[];
    uint32_t* A_hi = smem;
    uint32_t* A_lo = A_hi + SM_TILE_B32;
    uint32_t* B_hi = A_lo + SM_TILE_B32;
    uint32_t* B_lo = B_hi + SM_TILE_B32;

    const float* X = FROM_GX ? (const float*)g_x : Xin;
    const int tid = threadIdx.x;
    const int m0  = blockIdx.x * 128;

    // --- load X tile (128x128 f32), split to bf16 hi/lo in smem ---
    #pragma unroll
    for (int i = 0; i < 8; i++) {
        int id  = tid + i * 512;            // 0..4095 float4 slots
        int row = id >> 5;                  // 128 rows
        int kq  = id & 31;                  // float4 index (k = kq*4)
        float4 v = make_float4(0.f, 0.f, 0.f, 0.f);
        int gr = m0 + row;
        if (gr < nrows) v = *(const float4*)&X[(size_t)gr * D + kq * 4];
        __nv_bfloat162 h01, h23, l01, l23;
        h01.x = __float2bfloat16(v.x); h01.y = __float2bfloat16(v.y);
        h23.x = __float2bfloat16(v.z); h23.y = __float2bfloat16(v.w);
        l01.x = __float2bfloat16(v.x - __bfloat162float(h01.x));
        l01.y = __float2bfloat16(v.y - __bfloat162float(h01.y));
        l23.x = __float2bfloat16(v.z - __bfloat162float(h23.x));
        l23.y = __float2bfloat16(v.w - __bfloat162float(h23.y));
        int base = row * PITCH + kq * 2;
        A_hi[base]     = *(uint32_t*)&h01;
        A_hi[base + 1] = *(uint32_t*)&h23;
        A_lo[base]     = *(uint32_t*)&l01;
        A_lo[base + 1] = *(uint32_t*)&l23;
    }

    // --- copy W^T hi/lo ([n][k] bf16, row = 16 uint4) into padded smem ---
    {
        const uint4* wh = (const uint4*)&g_wt_hi[layer * D * D];
        const uint4* wl = (const uint4*)&g_wt_lo[layer * D * D];
        #pragma unroll
        for (int i = 0; i < 4; i++) {
            int id = tid + i * 512;         // 0..2047
            int n  = id >> 4;               // 128 rows
            int q  = id & 15;               // 16 uint4 per row
            // PITCH*4 = 272 bytes, multiple of 16 -> uint4 stores aligned
            *(uint4*)(B_hi + n * PITCH + q * 4) = wh[n * 16 + q];
            *(uint4*)(B_lo + n * PITCH + q * 4) = wl[n * 16 + q];
        }
    }
    __syncthreads();

    // --- warp MMA ---
    const int wid  = tid >> 5;
    const int lane = tid & 31;
    const int g    = lane >> 2;             // 0..7
    const int tig  = lane & 3;              // 0..3
    const int wm   = (wid & 3) * 32;        // warp row offset
    const int wn   = (wid >> 2) * 32;       // warp col offset

    float acc[2][4][4];
    #pragma unroll
    for (int mt = 0; mt < 2; mt++)
        #pragma unroll
        for (int nt = 0; nt < 4; nt++)
            #pragma unroll
            for (int e = 0; e < 4; e++) acc[mt][nt][e] = 0.f;

    #pragma unroll
    for (int split = 0; split < 3; split++) {
        const uint32_t* Ap = (split == 2) ? A_lo : A_hi;
        const uint32_t* Bp = (split == 1) ? B_lo : B_hi;
        #pragma unroll
        for (int step = 0; step < 8; step++) {
            int kb = step * 8;               // b32 offset for this k16 chunk
            uint32_t a[2][4], b[4][2];
            #pragma unroll
            for (int mt = 0; mt < 2; mt++) {
                int r = wm + mt * 16 + g;
                a[mt][0] = Ap[r * PITCH + kb + tig];
                a[mt][1] = Ap[(r + 8) * PITCH + kb + tig];
                a[mt][2] = Ap[r * PITCH + kb + tig + 4];
                a[mt][3] = Ap[(r + 8) * PITCH + kb + tig + 4];
            }
            #pragma unroll
            for (int nt = 0; nt < 4; nt++) {
                int c = wn + nt * 8 + g;
                b[nt][0] = Bp[c * PITCH + kb + tig];
                b[nt][1] = Bp[c * PITCH + kb + tig + 4];
            }
            #pragma unroll
            for (int mt = 0; mt < 2; mt++)
                #pragma unroll
                for (int nt = 0; nt < 4; nt++)
                    mma16816(acc[mt][nt], a[mt], b[nt]);
        }
    }

    // --- epilogue: scale by dinv[row], float2 stores ---
    #pragma unroll
    for (int mt = 0; mt < 2; mt++) {
        #pragma unroll
        for (int half = 0; half < 2; half++) {
            int row = m0 + wm + mt * 16 + g + half * 8;
            if (row >= nrows) continue;
            float dv = g_dinv[row];
            #pragma unroll
            for (int nt = 0; nt < 4; nt++) {
                float2 v;
                v.x = dv * acc[mt][nt][half * 2 + 0];
                v.y = dv * acc[mt][nt][half * 2 + 1];
                *(float2*)&g_buf[(size_t)row * D + wn + nt * 8 + tig * 2] = v;
            }
        }
    }
}

// ---------------- aggregate: out[v] = relu(dinv[v]*(g[v] + sum g[nbr]) + b) ----------------
template <bool TO_GX>
__global__ __launch_bounds__(256)
void aggregate(const float* __restrict__ bias, float* __restrict__ outp, int n) {
    int w    = (blockIdx.x * blockDim.x + threadIdx.x) >> 5;
    int lane = threadIdx.x & 31;
    if (w >= n) return;

    int beg = g_rowptr[w];
    int end = g_rowptr[w + 1];
    size_t col = (size_t)lane * 4;

    float4 acc = *(const float4*)&g_buf[(size_t)w * D + col];   // self-loop

    int e = beg;
    for (; e + 2 <= end; e += 2) {
        int s0 = __ldg(&g_csr[e]);
        int s1 = __ldg(&g_csr[e + 1]);
        float4 v0 = *(const float4*)&g_buf[(size_t)s0 * D + col];
        float4 v1 = *(const float4*)&g_buf[(size_t)s1 * D + col];
        acc.x += v0.x + v1.x;
        acc.y += v0.y + v1.y;
        acc.z += v0.z + v1.z;
        acc.w += v0.w + v1.w;
    }
    if (e < end) {
        int s0 = __ldg(&g_csr[e]);
        float4 v0 = *(const float4*)&g_buf[(size_t)s0 * D + col];
        acc.x += v0.x; acc.y += v0.y; acc.z += v0.z; acc.w += v0.w;
    }

    float dv = g_dinv[w];
    float4 b = *(const float4*)&bias[col];
    float4 r;
    r.x = fmaxf(fmaf(dv, acc.x, b.x), 0.f);
    r.y = fmaxf(fmaf(dv, acc.y, b.y), 0.f);
    r.z = fmaxf(fmaf(dv, acc.z, b.z), 0.f);
    r.w = fmaxf(fmaf(dv, acc.w, b.w), 0.f);

    float* out = TO_GX ? g_x : outp;
    *(float4*)&out[(size_t)w * D + col] = r;
}

// ---------------- launch ----------------
extern "C" void kernel_launch(void* const* d_in, const int* in_sizes, int n_in,
                              void* d_out, int out_size) {
    const float* node_fts = (const float*)d_in[0];
    const int*   edge     = (const int*)d_in[1];   // int32
    const float* W[3] = { (const float*)d_in[2], (const float*)d_in[4], (const float*)d_in[6] };
    const float* B[3] = { (const float*)d_in[3], (const float*)d_in[5], (const float*)d_in[7] };

    const int nrows = in_sizes[0] / D;
    const int E     = in_sizes[1] / 2;
    const int* src  = edge;
    const int* dst  = edge + E;

    static bool attr_done = false;
    if (!attr_done) {
        cudaFuncSetAttribute(gemm_mma<false>, cudaFuncAttributeMaxDynamicSharedMemorySize, SM_TOTAL);
        cudaFuncSetAttribute(gemm_mma<true>,  cudaFuncAttributeMaxDynamicSharedMemorySize, SM_TOTAL);
        attr_done = true;
    }

    const int scan_blocks = (nrows + SCAN_B - 1) / SCAN_B;

    // ---- CSR build + dinv + W^T splits (once per call) ----
    cnt_zero<<<(nrows + 255) / 256, 256>>>(nrows);
    cnt_count<<<(E + 255) / 256, 256>>>(dst, E);
    scanA<<<scan_blocks, SCAN_B>>>(nrows);
    scanB<<<1, MAX_BLOCKS>>>(scan_blocks, nrows);
    scanC<<<scan_blocks, SCAN_B>>>(nrows);
    fill_csr<<<(E + 255) / 256, 256>>>(src, dst, E);
    prep_wt<<<(3 * D * D + 255) / 256, 256>>>(W[0], W[1], W[2]);

    const int gemm_blocks = (nrows + 127) / 128;
    const int agg_blocks  = (nrows * 32 + 255) / 256;

    // Layer 1
    gemm_mma<false><<<gemm_blocks, 512, SM_TOTAL>>>(node_fts, 0, nrows);
    aggregate<true><<<agg_blocks, 256>>>(B[0], nullptr, nrows);
    // Layer 2
    gemm_mma<true><<<gemm_blocks, 512, SM_TOTAL>>>(nullptr, 1, nrows);
    aggregate<true><<<agg_blocks, 256>>>(B[1], nullptr, nrows);
    // Layer 3
    gemm_mma<true><<<gemm_blocks, 512, SM_TOTAL>>>(nullptr, 2, nrows);
    aggregate<false><<<agg_blocks, 256>>>(B[2], (float*)d_out, nrows);
}